// round 13
// baseline (speedup 1.0000x reference)
#include <cuda_runtime.h>

// RX gate on qubit 5 of a 12-qubit statevector, batch 4096.
//   out_re[j] = c*sr[j] + s*si[j^64]
//   out_im[j] = c*si[j] - s*sr[j^64]      (c = cos(theta/2), s = sin(theta/2))
// d_out layout: [out_re (4096*4096 floats) | out_im (4096*4096 floats)]
//
// FINAL — R3 configuration, best measured wall (45.06us) across 12 variants.
// The workload is at the mixed R/W HBM roofline: 256MB mandatory traffic per
// iteration (128MB reads + 128MB writebacks, zero reuse) at ~5.7TB/s
// sustained (~71% of spec; R/W-turnaround-limited ceiling). Exhaustively
// verified non-levers: per-thread MLP / thread shape (R2,R4), every L2
// eviction-hint configuration on loads and stores (R5-R10: zero cross-replay
// retention), 256-bit LDG/STG width (R7,R12: neutral at wall).
//
// Mapping: 128-element group = 32 float4s; lanes 0..15 cover the low half
// (bit6=0) contiguously, partner at +16 float4s. Every warp access is a
// contiguous 256B chunk -> minimal L1tex wavefronts, fully coalesced.

#define NELEM   (4096 * 4096)
#define NPAIRT  (NELEM / 8)     // one thread = 1 low float4 + 1 high float4

__global__ void __launch_bounds__(256)
rx_gate_kernel(const float4* __restrict__ sr4,
               const float4* __restrict__ si4,
               const float*  __restrict__ theta,
               float4* __restrict__ ore4,
               float4* __restrict__ oim4)
{
    int t = blockIdx.x * blockDim.x + threadIdx.x;

    float half = 0.5f * __ldg(theta);
    float s, c;
    sincosf(half, &s, &c);

    int grp = t >> 4;
    int w   = t & 15;
    int ilo = grp * 32 + w;    // element bit6 = 0
    int ihi = ilo + 16;        // element ^ 64

    float4 a_re = sr4[ilo];
    float4 b_re = sr4[ihi];
    float4 a_im = si4[ilo];
    float4 b_im = si4[ihi];

    float4 v;

    // out_re low: c*ar + s*bi
    v.x = fmaf(c, a_re.x, s * b_im.x);
    v.y = fmaf(c, a_re.y, s * b_im.y);
    v.z = fmaf(c, a_re.z, s * b_im.z);
    v.w = fmaf(c, a_re.w, s * b_im.w);
    __stcs(ore4 + ilo, v);

    // out_re high: c*br + s*ai
    v.x = fmaf(c, b_re.x, s * a_im.x);
    v.y = fmaf(c, b_re.y, s * a_im.y);
    v.z = fmaf(c, b_re.z, s * a_im.z);
    v.w = fmaf(c, b_re.w, s * a_im.w);
    __stcs(ore4 + ihi, v);

    // out_im low: c*ai - s*br
    v.x = fmaf(c, a_im.x, -s * b_re.x);
    v.y = fmaf(c, a_im.y, -s * b_re.y);
    v.z = fmaf(c, a_im.z, -s * b_re.z);
    v.w = fmaf(c, a_im.w, -s * b_re.w);
    __stcs(oim4 + ilo, v);

    // out_im high: c*bi - s*ar
    v.x = fmaf(c, b_im.x, -s * a_re.x);
    v.y = fmaf(c, b_im.y, -s * a_re.y);
    v.z = fmaf(c, b_im.z, -s * a_re.z);
    v.w = fmaf(c, b_im.w, -s * a_re.w);
    __stcs(oim4 + ihi, v);
}

extern "C" void kernel_launch(void* const* d_in, const int* in_sizes, int n_in,
                              void* d_out, int out_size)
{
    const float4* sr4   = (const float4*)d_in[0];
    const float4* si4   = (const float4*)d_in[1];
    const float*  theta = (const float*)d_in[2];

    float* out   = (float*)d_out;
    float4* ore4 = (float4*)out;
    float4* oim4 = (float4*)(out + NELEM);

    const int threads = 256;
    const int blocks  = NPAIRT / threads;   // 8192, exact
    rx_gate_kernel<<<blocks, threads>>>(sr4, si4, theta, ore4, oim4);
}

// round 14
// speedup vs baseline: 1.0021x; 1.0021x over previous
#include <cuda_runtime.h>

// RX gate on qubit 5 of a 12-qubit statevector, batch 4096.
//   out_re[j] = c*sr[j] + s*si[j^64]
//   out_im[j] = c*si[j] - s*sr[j^64]      (c = cos(theta/2), s = sin(theta/2))
// d_out layout: [out_re (4096*4096 floats) | out_im (4096*4096 floats)]
//
// R14: R3 mapping (best wall, 45.06us) with 1024-thread CTAs — the one
// launch-shape axis never varied. Workload is at the mixed R/W HBM roofline:
// 256MB mandatory traffic/iter at ~5.7TB/s sustained (~71% of spec,
// R/W-turnaround ceiling). Exhaustively verified non-levers: MLP/thread
// shape (R2,R4), all L2 eviction-hint configs (R5-R10, zero cross-replay
// retention), 256-bit LDG/STG (R7,R12).
//
// Mapping: 128-element group = 32 float4s; lanes 0..15 cover the low half
// (bit6=0) contiguously, partner at +16 float4s. Every warp access is a
// contiguous 256B chunk -> fully coalesced.

#define NELEM   (4096 * 4096)
#define NPAIRT  (NELEM / 8)     // one thread = 1 low float4 + 1 high float4

__global__ void __launch_bounds__(1024)
rx_gate_kernel(const float4* __restrict__ sr4,
               const float4* __restrict__ si4,
               const float*  __restrict__ theta,
               float4* __restrict__ ore4,
               float4* __restrict__ oim4)
{
    int t = blockIdx.x * blockDim.x + threadIdx.x;

    float half = 0.5f * __ldg(theta);
    float s, c;
    sincosf(half, &s, &c);

    int grp = t >> 4;
    int w   = t & 15;
    int ilo = grp * 32 + w;    // element bit6 = 0
    int ihi = ilo + 16;        // element ^ 64

    float4 a_re = sr4[ilo];
    float4 b_re = sr4[ihi];
    float4 a_im = si4[ilo];
    float4 b_im = si4[ihi];

    float4 v;

    // out_re low: c*ar + s*bi
    v.x = fmaf(c, a_re.x, s * b_im.x);
    v.y = fmaf(c, a_re.y, s * b_im.y);
    v.z = fmaf(c, a_re.z, s * b_im.z);
    v.w = fmaf(c, a_re.w, s * b_im.w);
    __stcs(ore4 + ilo, v);

    // out_re high: c*br + s*ai
    v.x = fmaf(c, b_re.x, s * a_im.x);
    v.y = fmaf(c, b_re.y, s * a_im.y);
    v.z = fmaf(c, b_re.z, s * a_im.z);
    v.w = fmaf(c, b_re.w, s * a_im.w);
    __stcs(ore4 + ihi, v);

    // out_im low: c*ai - s*br
    v.x = fmaf(c, a_im.x, -s * b_re.x);
    v.y = fmaf(c, a_im.y, -s * b_re.y);
    v.z = fmaf(c, a_im.z, -s * b_re.z);
    v.w = fmaf(c, a_im.w, -s * b_re.w);
    __stcs(oim4 + ilo, v);

    // out_im high: c*bi - s*ar
    v.x = fmaf(c, b_im.x, -s * a_re.x);
    v.y = fmaf(c, b_im.y, -s * a_re.y);
    v.z = fmaf(c, b_im.z, -s * a_re.z);
    v.w = fmaf(c, b_im.w, -s * a_re.w);
    __stcs(oim4 + ihi, v);
}

extern "C" void kernel_launch(void* const* d_in, const int* in_sizes, int n_in,
                              void* d_out, int out_size)
{
    const float4* sr4   = (const float4*)d_in[0];
    const float4* si4   = (const float4*)d_in[1];
    const float*  theta = (const float*)d_in[2];

    float* out   = (float*)d_out;
    float4* ore4 = (float4*)out;
    float4* oim4 = (float4*)(out + NELEM);

    const int threads = 1024;
    const int blocks  = NPAIRT / threads;   // 2048, exact
    rx_gate_kernel<<<blocks, threads>>>(sr4, si4, theta, ore4, oim4);
}

// round 15
// speedup vs baseline: 1.0071x; 1.0050x over previous
#include <cuda_runtime.h>

// RX gate on qubit 5 of a 12-qubit statevector, batch 4096.
//   out_re[j] = c*sr[j] + s*si[j^64]
//   out_im[j] = c*si[j] - s*sr[j^64]      (c = cos(theta/2), s = sin(theta/2))
// d_out layout: [out_re (4096*4096 floats) | out_im (4096*4096 floats)]
//
// FINAL — best measured configuration across 14 variants (45.06us wall).
// The dense state@M in the reference reduces to a bit-6 pairwise rotation:
// a pure streaming op with 256MB mandatory DRAM traffic per iteration
// (128MB one-touch reads + 128MB writebacks, zero reuse). Measured
// sustained mixed R/W: ~5.7TB/s (~71% of 8TB/s spec) — the HBM3e
// read/write-turnaround ceiling. Exhaustively verified non-levers:
//   - per-thread MLP / work size (R2, R4): neutral
//   - L2 eviction hints, every load/store combination and set size
//     (R5-R10): zero cross-replay retention
//   - 256-bit LDG/STG (R7, R12): neutral at wall
//   - CTA size 256 vs 1024 (R14): neutral
//
// Mapping: 128-element group = 32 float4s; lanes 0..15 cover the low half
// (bit6=0) contiguously, partner at +16 float4s. Every warp access is a
// contiguous 256B chunk -> minimal L1tex wavefronts, fully coalesced.

#define NELEM   (4096 * 4096)
#define NPAIRT  (NELEM / 8)     // one thread = 1 low float4 + 1 high float4

__global__ void __launch_bounds__(256)
rx_gate_kernel(const float4* __restrict__ sr4,
               const float4* __restrict__ si4,
               const float*  __restrict__ theta,
               float4* __restrict__ ore4,
               float4* __restrict__ oim4)
{
    int t = blockIdx.x * blockDim.x + threadIdx.x;

    float half = 0.5f * __ldg(theta);
    float s, c;
    sincosf(half, &s, &c);

    int grp = t >> 4;
    int w   = t & 15;
    int ilo = grp * 32 + w;    // element bit6 = 0
    int ihi = ilo + 16;        // element ^ 64

    float4 a_re = sr4[ilo];
    float4 b_re = sr4[ihi];
    float4 a_im = si4[ilo];
    float4 b_im = si4[ihi];

    float4 v;

    // out_re low: c*ar + s*bi
    v.x = fmaf(c, a_re.x, s * b_im.x);
    v.y = fmaf(c, a_re.y, s * b_im.y);
    v.z = fmaf(c, a_re.z, s * b_im.z);
    v.w = fmaf(c, a_re.w, s * b_im.w);
    __stcs(ore4 + ilo, v);

    // out_re high: c*br + s*ai
    v.x = fmaf(c, b_re.x, s * a_im.x);
    v.y = fmaf(c, b_re.y, s * a_im.y);
    v.z = fmaf(c, b_re.z, s * a_im.z);
    v.w = fmaf(c, b_re.w, s * a_im.w);
    __stcs(ore4 + ihi, v);

    // out_im low: c*ai - s*br
    v.x = fmaf(c, a_im.x, -s * b_re.x);
    v.y = fmaf(c, a_im.y, -s * b_re.y);
    v.z = fmaf(c, a_im.z, -s * b_re.z);
    v.w = fmaf(c, a_im.w, -s * b_re.w);
    __stcs(oim4 + ilo, v);

    // out_im high: c*bi - s*ar
    v.x = fmaf(c, b_im.x, -s * a_re.x);
    v.y = fmaf(c, b_im.y, -s * a_re.y);
    v.z = fmaf(c, b_im.z, -s * a_re.z);
    v.w = fmaf(c, b_im.w, -s * a_re.w);
    __stcs(oim4 + ihi, v);
}

extern "C" void kernel_launch(void* const* d_in, const int* in_sizes, int n_in,
                              void* d_out, int out_size)
{
    const float4* sr4   = (const float4*)d_in[0];
    const float4* si4   = (const float4*)d_in[1];
    const float*  theta = (const float*)d_in[2];

    float* out   = (float*)d_out;
    float4* ore4 = (float4*)out;
    float4* oim4 = (float4*)(out + NELEM);

    const int threads = 256;
    const int blocks  = NPAIRT / threads;   // 8192, exact
    rx_gate_kernel<<<blocks, threads>>>(sr4, si4, theta, ore4, oim4);
}